// round 9
// baseline (speedup 1.0000x reference)
#include <cuda_runtime.h>
#include <math.h>

#define BB 16
#define SS 100
#define VV 30000
#define HH 512
#define EE 300
#define TT 50
#define ML 50
#define DD 1836
#define VS 30100
#define NEGV (-1000000.0f)
#define NB4 469

__device__ float g_xT[(DD + HH) * BB];
__device__ float g_yT[1024 * BB];
__device__ float g_hidden[BB * HH];
__device__ float g_prehid[BB * HH];
__device__ float g_selread[BB * HH];
__device__ float g_css[BB * SS];
__device__ float g_cs[BB * VV];
__device__ float g_G[BB * VV];
__device__ float g_gi[BB * 1536];
__device__ float g_gh[BB * 1536];
__device__ float g_bmax[BB * NB4];
__device__ float g_bsum[BB * NB4];
__device__ float g_M[BB];
__device__ float g_Zi[BB];
__device__ unsigned long long g_amax[BB];
__device__ int g_presamp[BB], g_eos[BB], g_preseg[BB], g_index[BB], g_clen[BB];

__device__ __forceinline__ unsigned long long pk2(float lo, float hi) {
    unsigned long long r;
    asm("mov.b64 %0,{%1,%2};" : "=l"(r) : "f"(lo), "f"(hi));
    return r;
}
__device__ __forceinline__ void upk2(float& lo, float& hi, unsigned long long v) {
    asm("mov.b64 {%0,%1},%2;" : "=f"(lo), "=f"(hi) : "l"(v));
}
__device__ __forceinline__ void ffma2(unsigned long long& d, unsigned long long a,
                                      unsigned long long b) {
    asm("fma.rn.f32x2 %0,%1,%2,%0;" : "+l"(d) : "l"(a), "l"(b));
}

__global__ void k0_init(const float* __restrict__ z, const int* __restrict__ tpl,
                        float* __restrict__ out, float* __restrict__ oidx) {
    int tid = blockIdx.x * blockDim.x + threadIdx.x;
    int nth = gridDim.x * blockDim.x;
    for (int i = tid; i < BB * VS; i += nth) {
        int b = i / VS, j = i % VS;
        out[(size_t)b * ML * VS + j] = (j == 1) ? 1.f : 0.f;
    }
    for (int i = tid; i < BB * VV; i += nth) g_cs[i] = NEGV;
    for (int i = tid; i < BB * HH; i += nth) {
        g_hidden[i] = z[i]; g_prehid[i] = z[i]; g_selread[i] = 0.f;
    }
    if (tid < BB) {
        g_presamp[tid] = 1; g_eos[tid] = 1; g_preseg[tid] = tpl[tid * TT];
        g_index[tid] = 0; g_clen[tid] = 0;
        if (oidx) oidx[tid * ML] = 1.f;
    }
}

__global__ void k1_prep(int step, const float* __restrict__ enc,
                        const float* __restrict__ tmo, const float* __restrict__ emb,
                        const int* __restrict__ tpl, const int* __restrict__ inp,
                        float* __restrict__ oidx) {
    int b = blockIdx.x, tid = threadIdx.x;  // 512 threads
    __shared__ float s_sel[SS];
    __shared__ float s_red[512];
    __shared__ int s_ctrl[3];
    int samp = (step == 0) ? 1 : (0x7FFFFFFF - (int)(g_amax[b] & 0xFFFFFFFFull));

    if (step > 0) {
        if (tid < SS) s_sel[tid] = (inp[b * SS + tid] == samp) ? g_css[b * SS + tid] : 0.f;
        __syncthreads();
        s_red[tid] = (tid < SS) ? fabsf(s_sel[tid]) : 0.f;
        __syncthreads();
        for (int o = 256; o > 0; o >>= 1) {
            if (tid < o) s_red[tid] += s_red[tid + o];
            __syncthreads();
        }
        float inv = 1.f / fmaxf(s_red[0], 1e-12f);
        float acc = 0.f;
        const float* e = enc + (size_t)b * SS * HH + tid;
#pragma unroll 4
        for (int s = 0; s < SS; ++s) acc += s_sel[s] * e[(size_t)s * HH];
        g_selread[b * HH + tid] = acc * inv;
    }
    __syncthreads();
    if (tid == 0) {
        int ps = g_presamp[b], eos = g_eos[b];
        int eos_new = (ps == 6) ? eos : ps;
        int flag = (g_preseg[b] != 5) || (ps == 6) || (g_clen[b] > 20);
        int index = g_index[b] + (flag ? 1 : 0);
        g_clen[b] += flag ? 0 : 1;
        int seg = tpl[b * TT + index];
        int sampled = flag ? seg : samp;
        if (oidx) oidx[b * ML + step + 1] = (float)sampled;
        int keep = (sampled == 5) || (sampled == 6);
        int s2 = (sampled == 6) ? eos_new : sampled;
        g_presamp[b] = sampled; g_eos[b] = eos_new; g_preseg[b] = seg; g_index[b] = index;
        s_ctrl[0] = index; s_ctrl[1] = keep; s_ctrl[2] = (s2 > VV) ? 3 : s2;
    }
    __syncthreads();
    int index = s_ctrl[0], keep = s_ctrl[1], ie = s_ctrl[2];
    float ph = keep ? g_prehid[b * HH + tid] : g_hidden[b * HH + tid];
    g_prehid[b * HH + tid] = ph;
    g_xT[tid * BB + b] = ph;
    g_xT[(HH + tid) * BB + b] = tmo[((size_t)b * TT + index) * HH + tid];
    g_xT[(2 * HH + tid) * BB + b] = g_selread[b * HH + tid];
    if (tid < EE) g_xT[(3 * HH + tid) * BB + b] = emb[(size_t)ie * EE + tid];
    g_xT[(DD + tid) * BB + b] = ph;
}

// GRU matvecs (gi: 1536x1836, gh: 1536x512), batch-shared, f32x2 over batch pairs
__global__ void k2_mm(const float* __restrict__ wih, const float* __restrict__ whh) {
    __shared__ float ws[64][68];
    __shared__ unsigned long long ysp[8][64];
    int blk = blockIdx.x, tid = threadIdx.x;
    int ih = blk < 24;
    const float* W = ih ? wih : whh;
    int ld = ih ? DD : HH, koff = ih ? 0 : DD, nk = ld;
    int row0 = (ih ? blk : blk - 24) * 64;
    float* outp = ih ? g_gi : g_gh;
    int ty = tid >> 2, tx = tid & 3;
    unsigned long long aA = 0, aB = 0;
    int nc = (nk + 63) >> 6;
    for (int c = 0; c < nc; ++c) {
        int k0 = c * 64;
        for (int l = tid; l < 1024; l += 256) {
            int r = l >> 4, kq = (l & 15) * 4;
            const float* wr = W + (size_t)(row0 + r) * ld + k0 + kq;
            float4 v;
            v.x = (k0 + kq < nk) ? wr[0] : 0.f;
            v.y = (k0 + kq + 1 < nk) ? wr[1] : 0.f;
            v.z = (k0 + kq + 2 < nk) ? wr[2] : 0.f;
            v.w = (k0 + kq + 3 < nk) ? wr[3] : 0.f;
            *(float4*)&ws[r][kq] = v;
        }
        for (int l = tid; l < 512; l += 256) {
            int p = l >> 6, k = l & 63;
            float lo = 0.f, hi = 0.f;
            if (k0 + k < nk) {
                lo = g_xT[(koff + k0 + k) * BB + 2 * p];
                hi = g_xT[(koff + k0 + k) * BB + 2 * p + 1];
            }
            ysp[p][k] = pk2(lo, hi);
        }
        __syncthreads();
#pragma unroll
        for (int kk = 0; kk < 64; kk += 2) {
            float2 w = *(float2*)&ws[ty][kk];
            unsigned long long p0 = pk2(w.x, w.x), p1 = pk2(w.y, w.y);
            ffma2(aA, p0, ysp[tx][kk]); ffma2(aA, p1, ysp[tx][kk + 1]);
            ffma2(aB, p0, ysp[tx + 4][kk]); ffma2(aB, p1, ysp[tx + 4][kk + 1]);
        }
        __syncthreads();
    }
    float f0, f1, f2, f3;
    upk2(f0, f1, aA); upk2(f2, f3, aB);
    int r = row0 + ty;
    outp[(2 * tx) * 1536 + r] = f0;
    outp[(2 * tx + 1) * 1536 + r] = f1;
    outp[(2 * tx + 8) * 1536 + r] = f2;
    outp[(2 * tx + 9) * 1536 + r] = f3;
}

__global__ void k2_gate(const float* __restrict__ bi, const float* __restrict__ bh) {
    int idx = blockIdx.x * blockDim.x + threadIdx.x;  // 8192
    int b = idx >> 9, h = idx & 511, o = b * 1536;
    float r = 1.f / (1.f + expf(-(g_gi[o + h] + bi[h] + g_gh[o + h] + bh[h])));
    float zg = 1.f / (1.f + expf(-(g_gi[o + 512 + h] + bi[512 + h] + g_gh[o + 512 + h] + bh[512 + h])));
    float n = tanhf(g_gi[o + 1024 + h] + bi[1024 + h] + r * (g_gh[o + 1024 + h] + bh[1024 + h]));
    float hp = g_prehid[b * HH + h];
    float hn = (1.f - zg) * n + zg * hp;
    g_hidden[b * HH + h] = hn;
    g_yT[(512 + h) * BB + b] = hn;
}

__global__ void k3_attn(const float* __restrict__ enc, const float* __restrict__ aw,
                        const float* __restrict__ ab, const float* __restrict__ cw,
                        const float* __restrict__ cb, const int* __restrict__ inp) {
    int b = blockIdx.x, tid = threadIdx.x;  // 256
    __shared__ float s_hid[HH], s_th[HH], s_th2[HH], s_sc[SS], s_css[SS];
    __shared__ int s_inp[SS];
    for (int i = tid; i < HH; i += 256) s_hid[i] = g_hidden[b * HH + i];
    if (tid < SS) s_inp[tid] = inp[b * SS + tid];
    __syncthreads();
    for (int i = tid; i < HH; i += 256) {
        float a = 0.f, c = 0.f;
        const float* wa = aw + (size_t)i * HH;
        const float* wc = cw + (size_t)i * HH;
#pragma unroll 4
        for (int k = 0; k < HH; k += 4) {
            float4 w1 = *(const float4*)&wa[k];
            float4 w2 = *(const float4*)&wc[k];
            a += w1.x * s_hid[k] + w1.y * s_hid[k + 1] + w1.z * s_hid[k + 2] + w1.w * s_hid[k + 3];
            c += w2.x * s_hid[k] + w2.y * s_hid[k + 1] + w2.z * s_hid[k + 2] + w2.w * s_hid[k + 3];
        }
        s_th[i] = a + ab[i];
        s_th2[i] = c + cb[i];
    }
    __syncthreads();
    int wid = tid >> 5, lane = tid & 31;
    for (int s = wid; s < SS; s += 8) {
        const float* e = enc + ((size_t)b * SS + s) * HH;
        float a = 0.f, c = 0.f;
        for (int k = lane; k < HH; k += 32) {
            float ev = e[k];
            a += ev * s_th[k];
            c += ev * s_th2[k];
        }
        for (int o = 16; o > 0; o >>= 1) {
            a += __shfl_down_sync(0xffffffffu, a, o);
            c += __shfl_down_sync(0xffffffffu, c, o);
        }
        if (lane == 0) { s_sc[s] = a; s_css[s] = c; }
    }
    __syncthreads();
    if (wid == 0) {
        float m = -3.4e38f;
        for (int s = lane; s < SS; s += 32) m = fmaxf(m, s_sc[s]);
        for (int o = 16; o > 0; o >>= 1) m = fmaxf(m, __shfl_xor_sync(0xffffffffu, m, o));
        float sum = 0.f;
        for (int s = lane; s < SS; s += 32) {
            float e = expf(s_sc[s] - m);
            s_sc[s] = e; sum += e;
        }
        for (int o = 16; o > 0; o >>= 1) sum += __shfl_xor_sync(0xffffffffu, sum, o);
        float inv = 1.f / sum;
        for (int s = lane; s < SS; s += 32) s_sc[s] *= inv;
    }
    __syncthreads();
    for (int h = tid; h < HH; h += 256) {
        float acc = 0.f;
        const float* e = enc + (size_t)b * SS * HH + h;
#pragma unroll 4
        for (int s = 0; s < SS; ++s) acc += s_sc[s] * e[(size_t)s * HH];
        g_yT[h * BB + b] = acc;
    }
    if (tid < SS) g_css[b * SS + tid] = s_css[tid];
    for (int s = tid; s < SS; s += 256) {
        int t = s_inp[s];
        if (t != 0) {
            float sum = 0.f;
            for (int s2 = 0; s2 < SS; ++s2)
                if (s_inp[s2] == t) sum += s_css[s2];
            g_cs[(size_t)b * VV + t] = sum;
        }
    }
}

// gen GEMM 30000x1024 x 16 batches, f32x2 batch pairs + online softmax partials
__global__ void k4_gen(const float* __restrict__ ow, const float* __restrict__ ob) {
    __shared__ float ws[64][68];
    __shared__ unsigned long long ysp[8][64];
    __shared__ float s_m[16][64], s_s[16][64];
    int blk = blockIdx.x, tid = threadIdx.x;
    int v0 = blk * 64;
    int ty = tid >> 2, tx = tid & 3;
    unsigned long long aA = 0, aB = 0;
    for (int c = 0; c < 16; ++c) {
        int k0 = c * 64;
        for (int l = tid; l < 1024; l += 256) {
            int r = l >> 4, kq = (l & 15) * 4;
            float4 v = make_float4(0.f, 0.f, 0.f, 0.f);
            if (v0 + r < VV) v = *(const float4*)&ow[(size_t)(v0 + r) * 1024 + k0 + kq];
            *(float4*)&ws[r][kq] = v;
        }
        for (int l = tid; l < 512; l += 256) {
            int p = l >> 6, k = l & 63;
            ysp[p][k] = pk2(g_yT[(k0 + k) * BB + 2 * p], g_yT[(k0 + k) * BB + 2 * p + 1]);
        }
        __syncthreads();
#pragma unroll
        for (int kk = 0; kk < 64; kk += 2) {
            float2 w = *(float2*)&ws[ty][kk];
            unsigned long long p0 = pk2(w.x, w.x), p1 = pk2(w.y, w.y);
            ffma2(aA, p0, ysp[tx][kk]); ffma2(aA, p1, ysp[tx][kk + 1]);
            ffma2(aB, p0, ysp[tx + 4][kk]); ffma2(aB, p1, ysp[tx + 4][kk + 1]);
        }
        __syncthreads();
    }
    int row = v0 + ty;
    bool val = row < VV;
    float obv = val ? ob[row] : 0.f;
    float g[4], cc[4];
    upk2(g[0], g[1], aA); upk2(g[2], g[3], aB);
    int bs[4] = {2 * tx, 2 * tx + 1, 2 * tx + 8, 2 * tx + 9};
#pragma unroll
    for (int j = 0; j < 4; ++j) {
        float gg = g[j] + obv;
        if (!val || row == 0) gg = NEGV;
        g[j] = gg;
        if (val) {
            g_G[(size_t)bs[j] * VV + row] = gg;
            cc[j] = g_cs[(size_t)bs[j] * VV + row];
        } else cc[j] = NEGV;
        float m = fmaxf(gg, cc[j]);
        s_m[bs[j]][ty] = m;
        s_s[bs[j]][ty] = expf(gg - m) + expf(cc[j] - m);
    }
    __syncthreads();
    if (tid < 16) {
        float M = -3.4e38f;
        for (int t = 0; t < 64; ++t) M = fmaxf(M, s_m[tid][t]);
        float S = 0.f;
        for (int t = 0; t < 64; ++t) S += s_s[tid][t] * expf(s_m[tid][t] - M);
        g_bmax[tid * NB4 + blk] = M;
        g_bsum[tid * NB4 + blk] = S;
    }
}

__global__ void k5_comb() {
    int tid = threadIdx.x, b = tid >> 5, lane = tid & 31;  // 512 threads
    float M = -3.4e38f;
    for (int i = lane; i < NB4; i += 32) M = fmaxf(M, g_bmax[b * NB4 + i]);
    for (int o = 16; o > 0; o >>= 1) M = fmaxf(M, __shfl_xor_sync(0xffffffffu, M, o));
    float S = 0.f;
    for (int i = lane; i < NB4; i += 32) S += g_bsum[b * NB4 + i] * expf(g_bmax[b * NB4 + i] - M);
    for (int o = 16; o > 0; o >>= 1) S += __shfl_xor_sync(0xffffffffu, S, o);
    if (lane == 0) {
        g_M[b] = M;
        g_Zi[b] = 1.f / S;
        g_amax[b] = 0ull;
    }
}

__global__ void k6_final(int step, float* __restrict__ out) {
    __shared__ unsigned long long s_k[256];
    int b = blockIdx.y, tid = threadIdx.x;
    int v = blockIdx.x * 256 + tid;
    float* orow = out + ((size_t)b * ML + step + 1) * VS;
    unsigned long long key = 0ull;
    if (v < VV) {
        float M = g_M[b], Zi = g_Zi[b];
        float f = (expf(g_G[(size_t)b * VV + v] - M) + expf(g_cs[(size_t)b * VV + v] - M)) * Zi;
        orow[v] = f;
        unsigned int u = __float_as_uint(f);
        unsigned int mono = u ^ ((u >> 31) ? 0xFFFFFFFFu : 0x80000000u);
        key = ((unsigned long long)mono << 32) | (unsigned int)(0x7FFFFFFF - v);
    } else if (v < VS) {
        orow[v] = 0.f;
    }
    s_k[tid] = key;
    __syncthreads();
    for (int o = 128; o > 0; o >>= 1) {
        if (tid < o) s_k[tid] = max(s_k[tid], s_k[tid + o]);
        __syncthreads();
    }
    if (tid == 0 && s_k[0]) atomicMax(&g_amax[b], s_k[0]);
}

extern "C" void kernel_launch(void* const* d_in, const int* in_sizes, int n_in,
                              void* d_out, int out_size) {
    const float* enc = (const float*)d_in[0];
    const float* tmo = (const float*)d_in[1];
    const float* z = (const float*)d_in[2];
    const float* emb = (const float*)d_in[3];
    const float* wih = (const float*)d_in[4];
    const float* whh = (const float*)d_in[5];
    const float* bih = (const float*)d_in[6];
    const float* bhh = (const float*)d_in[7];
    const float* aw = (const float*)d_in[8];
    const float* ab = (const float*)d_in[9];
    const float* cw = (const float*)d_in[10];
    const float* cb = (const float*)d_in[11];
    const float* ow = (const float*)d_in[12];
    const float* obp = (const float*)d_in[13];
    const int* tpl = (const int*)d_in[14];
    const int* inp = (const int*)d_in[15];
    float* out = (float*)d_out;
    float* oidx = (out_size >= BB * ML * VS + BB * ML) ? out + (size_t)BB * ML * VS : nullptr;

    k0_init<<<256, 256>>>(z, tpl, out, oidx);
    for (int s = 0; s < ML - 1; ++s) {
        k1_prep<<<BB, 512>>>(s, enc, tmo, emb, tpl, inp, oidx);
        k2_mm<<<48, 256>>>(wih, whh);
        k2_gate<<<32, 256>>>(bih, bhh);
        k3_attn<<<BB, 256>>>(enc, aw, ab, cw, cb, inp);
        k4_gen<<<NB4, 256>>>(ow, obp);
        k5_comb<<<1, 512>>>();
        k6_final<<<dim3(118, BB), 256>>>(s, out);
    }
}

// round 11
// speedup vs baseline: 1.0221x; 1.0221x over previous
#include <cuda_runtime.h>
#include <math.h>

#define BB 16
#define SS 100
#define VV 30000
#define HH 512
#define EE 300
#define TT 50
#define ML 50
#define DD 1836
#define VS 30100
#define NEGV (-1000000.0f)
#define NB4 469

__device__ float g_xT[(DD + HH) * BB];
__device__ float g_yT[1024 * BB];
__device__ float g_hidden[BB * HH];
__device__ float g_prehid[BB * HH];
__device__ float g_selread[BB * HH];
__device__ float g_css[BB * SS];
__device__ float g_cs[BB * VV];
__device__ float g_G[BB * VV];
__device__ float g_gi[BB * 1536];
__device__ float g_gh[BB * 1536];
__device__ float g_bmax[BB * NB4];
__device__ float g_bsum[BB * NB4];
__device__ unsigned long long g_amax[BB];
__device__ int g_presamp[BB], g_eos[BB], g_preseg[BB], g_index[BB], g_clen[BB];

__device__ __forceinline__ unsigned long long pk2(float lo, float hi) {
    unsigned long long r;
    asm("mov.b64 %0,{%1,%2};" : "=l"(r) : "f"(lo), "f"(hi));
    return r;
}
__device__ __forceinline__ void upk2(float& lo, float& hi, unsigned long long v) {
    asm("mov.b64 {%0,%1},%2;" : "=f"(lo), "=f"(hi) : "l"(v));
}
__device__ __forceinline__ void ffma2(unsigned long long& d, unsigned long long a,
                                      unsigned long long b) {
    asm("fma.rn.f32x2 %0,%1,%2,%0;" : "+l"(d) : "l"(a), "l"(b));
}

// control + selread + build x ; step 0 also does all per-launch init
__global__ __launch_bounds__(512) void k1_prep(int step, const float* __restrict__ z,
        const float* __restrict__ enc, const float* __restrict__ tmo,
        const float* __restrict__ emb, const int* __restrict__ tpl,
        const int* __restrict__ inp, float* __restrict__ out, float* __restrict__ oidx) {
    int b = blockIdx.x, tid = threadIdx.x;  // 512 threads
    __shared__ float s_sel[SS];
    __shared__ float s_red[512];
    __shared__ int s_ctrl[3];

    if (step == 0) {
        float* orow = out + (size_t)b * ML * VS;
        for (int j = tid; j < VS; j += 512) orow[j] = (j == 1) ? 1.f : 0.f;
        for (int v = tid; v < VV; v += 512) g_cs[(size_t)b * VV + v] = NEGV;
        g_hidden[b * HH + tid] = z[b * HH + tid];
        g_prehid[b * HH + tid] = z[b * HH + tid];
        g_selread[b * HH + tid] = 0.f;
        if (tid == 0 && oidx) oidx[b * ML] = 1.f;
    }

    int samp = (step == 0) ? 1 : (0x7FFFFFFF - (int)(g_amax[b] & 0xFFFFFFFFull));
    if (step > 0) {
        if (tid < SS) s_sel[tid] = (inp[b * SS + tid] == samp) ? g_css[b * SS + tid] : 0.f;
        __syncthreads();
        s_red[tid] = (tid < SS) ? fabsf(s_sel[tid]) : 0.f;
        __syncthreads();
        for (int o = 256; o > 0; o >>= 1) {
            if (tid < o) s_red[tid] += s_red[tid + o];
            __syncthreads();
        }
        float inv = 1.f / fmaxf(s_red[0], 1e-12f);
        float acc = 0.f;
        const float* e = enc + (size_t)b * SS * HH + tid;
#pragma unroll 4
        for (int s = 0; s < SS; ++s) acc += s_sel[s] * e[(size_t)s * HH];
        g_selread[b * HH + tid] = acc * inv;
    }
    __syncthreads();
    if (tid == 0) {
        int ps, eos, preseg, index, clen;
        if (step == 0) { ps = 1; eos = 1; preseg = tpl[b * TT]; index = 0; clen = 0; }
        else { ps = g_presamp[b]; eos = g_eos[b]; preseg = g_preseg[b]; index = g_index[b]; clen = g_clen[b]; }
        int eos_new = (ps == 6) ? eos : ps;
        int flag = (preseg != 5) || (ps == 6) || (clen > 20);
        index += flag ? 1 : 0;
        clen += flag ? 0 : 1;
        int seg = tpl[b * TT + index];
        int sampled = flag ? seg : samp;
        if (oidx) oidx[b * ML + step + 1] = (float)sampled;
        int keep = (sampled == 5) || (sampled == 6);
        int s2 = (sampled == 6) ? eos_new : sampled;
        g_presamp[b] = sampled; g_eos[b] = eos_new; g_preseg[b] = seg;
        g_index[b] = index; g_clen[b] = clen;
        g_amax[b] = 0ull;   // safe: all g_amax reads done above
        s_ctrl[0] = index; s_ctrl[1] = keep; s_ctrl[2] = (s2 > VV) ? 3 : s2;
    }
    __syncthreads();
    int index = s_ctrl[0], keep = s_ctrl[1], ie = s_ctrl[2];
    float ph = keep ? g_prehid[b * HH + tid] : g_hidden[b * HH + tid];
    g_prehid[b * HH + tid] = ph;
    g_xT[tid * BB + b] = ph;
    g_xT[(HH + tid) * BB + b] = tmo[((size_t)b * TT + index) * HH + tid];
    g_xT[(2 * HH + tid) * BB + b] = g_selread[b * HH + tid];
    if (tid < EE) g_xT[(3 * HH + tid) * BB + b] = emb[(size_t)ie * EE + tid];
    g_xT[(DD + tid) * BB + b] = ph;
}

// GRU matvecs, batch-shared, f32x2 batch pairs
__global__ __launch_bounds__(256) void k2_mm(const float* __restrict__ wih,
                                             const float* __restrict__ whh) {
    __shared__ float ws[64][68];
    __shared__ unsigned long long ysp[8][64];
    int blk = blockIdx.x, tid = threadIdx.x;
    int ih = blk < 24;
    const float* W = ih ? wih : whh;
    int nk = ih ? DD : HH, koff = ih ? 0 : DD;
    int row0 = (ih ? blk : blk - 24) * 64;
    float* outp = ih ? g_gi : g_gh;
    int ty = tid >> 2, tx = tid & 3;
    unsigned long long aA = 0, aB = 0;
    int nc = (nk + 63) >> 6;
    for (int c = 0; c < nc; ++c) {
        int k0 = c * 64;
        for (int l = tid; l < 1024; l += 256) {
            int r = l >> 4, kq = (l & 15) * 4;
            float4 v = make_float4(0.f, 0.f, 0.f, 0.f);
            if (k0 + kq + 3 < nk)   // nk % 4 == 0 -> whole-vector predicate
                v = *(const float4*)&W[(size_t)(row0 + r) * nk + k0 + kq];
            *(float4*)&ws[r][kq] = v;
        }
        for (int l = tid; l < 512; l += 256) {
            int p = l >> 6, k = l & 63;
            float lo = 0.f, hi = 0.f;
            if (k0 + k < nk) {
                lo = g_xT[(koff + k0 + k) * BB + 2 * p];
                hi = g_xT[(koff + k0 + k) * BB + 2 * p + 1];
            }
            ysp[p][k] = pk2(lo, hi);
        }
        __syncthreads();
#pragma unroll
        for (int kk = 0; kk < 64; kk += 2) {
            float2 w = *(float2*)&ws[ty][kk];
            unsigned long long p0 = pk2(w.x, w.x), p1 = pk2(w.y, w.y);
            ffma2(aA, p0, ysp[tx][kk]); ffma2(aA, p1, ysp[tx][kk + 1]);
            ffma2(aB, p0, ysp[tx + 4][kk]); ffma2(aB, p1, ysp[tx + 4][kk + 1]);
        }
        __syncthreads();
    }
    float f0, f1, f2, f3;
    upk2(f0, f1, aA); upk2(f2, f3, aB);
    int r = row0 + ty;
    outp[(2 * tx) * 1536 + r] = f0;
    outp[(2 * tx + 1) * 1536 + r] = f1;
    outp[(2 * tx + 8) * 1536 + r] = f2;
    outp[(2 * tx + 9) * 1536 + r] = f3;
}

// fused GRU gates + attention + copy scores
__global__ __launch_bounds__(256) void k3_attn(const float* __restrict__ enc,
        const float* __restrict__ bi, const float* __restrict__ bh,
        const float* __restrict__ aw, const float* __restrict__ ab,
        const float* __restrict__ cw, const float* __restrict__ cb,
        const int* __restrict__ inp) {
    int b = blockIdx.x, tid = threadIdx.x;  // 256
    __shared__ float s_hid[HH], s_th[HH], s_th2[HH], s_sc[SS], s_css[SS];
    __shared__ int s_inp[SS];
    int o = b * 1536;
    for (int h = tid; h < HH; h += 256) {
        float r = 1.f / (1.f + expf(-(g_gi[o + h] + bi[h] + g_gh[o + h] + bh[h])));
        float zg = 1.f / (1.f + expf(-(g_gi[o + 512 + h] + bi[512 + h] + g_gh[o + 512 + h] + bh[512 + h])));
        float n = tanhf(g_gi[o + 1024 + h] + bi[1024 + h] + r * (g_gh[o + 1024 + h] + bh[1024 + h]));
        float hp = g_prehid[b * HH + h];
        float hn = (1.f - zg) * n + zg * hp;
        g_hidden[b * HH + h] = hn;
        g_yT[(512 + h) * BB + b] = hn;
        s_hid[h] = hn;
    }
    if (tid < SS) s_inp[tid] = inp[b * SS + tid];
    __syncthreads();
    for (int i = tid; i < HH; i += 256) {
        float a = 0.f, c = 0.f;
        const float* wa = aw + (size_t)i * HH;
        const float* wc = cw + (size_t)i * HH;
#pragma unroll 4
        for (int k = 0; k < HH; k += 4) {
            float4 w1 = *(const float4*)&wa[k];
            float4 w2 = *(const float4*)&wc[k];
            a += w1.x * s_hid[k] + w1.y * s_hid[k + 1] + w1.z * s_hid[k + 2] + w1.w * s_hid[k + 3];
            c += w2.x * s_hid[k] + w2.y * s_hid[k + 1] + w2.z * s_hid[k + 2] + w2.w * s_hid[k + 3];
        }
        s_th[i] = a + ab[i];
        s_th2[i] = c + cb[i];
    }
    __syncthreads();
    int wid = tid >> 5, lane = tid & 31;
    for (int s = wid; s < SS; s += 8) {
        const float* e = enc + ((size_t)b * SS + s) * HH;
        float a = 0.f, c = 0.f;
        for (int k = lane; k < HH; k += 32) {
            float ev = e[k];
            a += ev * s_th[k];
            c += ev * s_th2[k];
        }
        for (int off = 16; off > 0; off >>= 1) {
            a += __shfl_down_sync(0xffffffffu, a, off);
            c += __shfl_down_sync(0xffffffffu, c, off);
        }
        if (lane == 0) { s_sc[s] = a; s_css[s] = c; }
    }
    __syncthreads();
    if (wid == 0) {
        float m = -3.4e38f;
        for (int s = lane; s < SS; s += 32) m = fmaxf(m, s_sc[s]);
        for (int off = 16; off > 0; off >>= 1) m = fmaxf(m, __shfl_xor_sync(0xffffffffu, m, off));
        float sum = 0.f;
        for (int s = lane; s < SS; s += 32) {
            float e = expf(s_sc[s] - m);
            s_sc[s] = e; sum += e;
        }
        for (int off = 16; off > 0; off >>= 1) sum += __shfl_xor_sync(0xffffffffu, sum, off);
        float inv = 1.f / sum;
        for (int s = lane; s < SS; s += 32) s_sc[s] *= inv;
    }
    __syncthreads();
    for (int h = tid; h < HH; h += 256) {
        float acc = 0.f;
        const float* e = enc + (size_t)b * SS * HH + h;
#pragma unroll 4
        for (int s = 0; s < SS; ++s) acc += s_sc[s] * e[(size_t)s * HH];
        g_yT[h * BB + b] = acc;
    }
    if (tid < SS) g_css[b * SS + tid] = s_css[tid];
    for (int s = tid; s < SS; s += 256) {
        int t = s_inp[s];
        if (t != 0) {
            float sum = 0.f;
            for (int s2 = 0; s2 < SS; ++s2)
                if (s_inp[s2] == t) sum += s_css[s2];
            g_cs[(size_t)b * VV + t] = sum;
        }
    }
}

// gen GEMM 30000x1024 x 16 batches, f32x2 batch pairs + online softmax partials
__global__ __launch_bounds__(256) void k4_gen(const float* __restrict__ ow,
                                              const float* __restrict__ ob) {
    __shared__ float ws[64][68];
    __shared__ unsigned long long ysp[8][64];
    __shared__ float s_m[16][64], s_s[16][64];
    int blk = blockIdx.x, tid = threadIdx.x;
    int v0 = blk * 64;
    int ty = tid >> 2, tx = tid & 3;
    unsigned long long aA = 0, aB = 0;
    for (int c = 0; c < 16; ++c) {
        int k0 = c * 64;
        for (int l = tid; l < 1024; l += 256) {
            int r = l >> 4, kq = (l & 15) * 4;
            float4 v = make_float4(0.f, 0.f, 0.f, 0.f);
            if (v0 + r < VV) v = *(const float4*)&ow[(size_t)(v0 + r) * 1024 + k0 + kq];
            *(float4*)&ws[r][kq] = v;
        }
        for (int l = tid; l < 512; l += 256) {
            int p = l >> 6, k = l & 63;
            ysp[p][k] = pk2(g_yT[(k0 + k) * BB + 2 * p], g_yT[(k0 + k) * BB + 2 * p + 1]);
        }
        __syncthreads();
#pragma unroll
        for (int kk = 0; kk < 64; kk += 2) {
            float2 w = *(float2*)&ws[ty][kk];
            unsigned long long p0 = pk2(w.x, w.x), p1 = pk2(w.y, w.y);
            ffma2(aA, p0, ysp[tx][kk]); ffma2(aA, p1, ysp[tx][kk + 1]);
            ffma2(aB, p0, ysp[tx + 4][kk]); ffma2(aB, p1, ysp[tx + 4][kk + 1]);
        }
        __syncthreads();
    }
    int row = v0 + ty;
    bool val = row < VV;
    float obv = val ? ob[row] : 0.f;
    float g[4], cc[4];
    upk2(g[0], g[1], aA); upk2(g[2], g[3], aB);
    int bs[4] = {2 * tx, 2 * tx + 1, 2 * tx + 8, 2 * tx + 9};
#pragma unroll
    for (int j = 0; j < 4; ++j) {
        float gg = g[j] + obv;
        if (!val || row == 0) gg = NEGV;
        if (val) {
            g_G[(size_t)bs[j] * VV + row] = gg;
            cc[j] = g_cs[(size_t)bs[j] * VV + row];
        } else cc[j] = NEGV;
        float m = fmaxf(gg, cc[j]);
        s_m[bs[j]][ty] = m;
        s_s[bs[j]][ty] = expf(gg - m) + expf(cc[j] - m);
    }
    __syncthreads();
    if (tid < 16) {
        float M = -3.4e38f;
        for (int t = 0; t < 64; ++t) M = fmaxf(M, s_m[tid][t]);
        float S = 0.f;
        for (int t = 0; t < 64; ++t) S += s_s[tid][t] * expf(s_m[tid][t] - M);
        g_bmax[tid * NB4 + blk] = M;
        g_bsum[tid * NB4 + blk] = S;
    }
}

// per-block softmax combine + final probs + argmax
__global__ __launch_bounds__(256) void k6_final(int step, float* __restrict__ out) {
    __shared__ float s_red[256];
    __shared__ unsigned long long s_k[256];
    __shared__ float s_M, s_Zi;
    int b = blockIdx.y, tid = threadIdx.x;
    float lm = -3.4e38f;
    for (int i = tid; i < NB4; i += 256) lm = fmaxf(lm, g_bmax[b * NB4 + i]);
    s_red[tid] = lm; __syncthreads();
    for (int o = 128; o > 0; o >>= 1) {
        if (tid < o) s_red[tid] = fmaxf(s_red[tid], s_red[tid + o]);
        __syncthreads();
    }
    if (tid == 0) s_M = s_red[0];
    __syncthreads();
    float M = s_M;
    float ls = 0.f;
    for (int i = tid; i < NB4; i += 256) ls += g_bsum[b * NB4 + i] * expf(g_bmax[b * NB4 + i] - M);
    s_red[tid] = ls; __syncthreads();
    for (int o = 128; o > 0; o >>= 1) {
        if (tid < o) s_red[tid] += s_red[tid + o];
        __syncthreads();
    }
    if (tid == 0) s_Zi = 1.f / s_red[0];
    __syncthreads();
    float Zi = s_Zi;

    int v = blockIdx.x * 256 + tid;
    float* orow = out + ((size_t)b * ML + step + 1) * VS;
    unsigned long long key = 0ull;
    if (v < VV) {
        float f = (expf(g_G[(size_t)b * VV + v] - M) + expf(g_cs[(size_t)b * VV + v] - M)) * Zi;
        orow[v] = f;
        unsigned int u = __float_as_uint(f);
        unsigned int mono = u ^ ((u >> 31) ? 0xFFFFFFFFu : 0x80000000u);
        key = ((unsigned long long)mono << 32) | (unsigned int)(0x7FFFFFFF - v);
    } else if (v < VS) {
        orow[v] = 0.f;
    }
    s_k[tid] = key;
    __syncthreads();
    for (int o = 128; o > 0; o >>= 1) {
        if (tid < o) s_k[tid] = max(s_k[tid], s_k[tid + o]);
        __syncthreads();
    }
    if (tid == 0 && s_k[0]) atomicMax(&g_amax[b], s_k[0]);
}

extern "C" void kernel_launch(void* const* d_in, const int* in_sizes, int n_in,
                              void* d_out, int out_size) {
    const float* enc = (const float*)d_in[0];
    const float* tmo = (const float*)d_in[1];
    const float* z = (const float*)d_in[2];
    const float* emb = (const float*)d_in[3];
    const float* wih = (const float*)d_in[4];
    const float* whh = (const float*)d_in[5];
    const float* bih = (const float*)d_in[6];
    const float* bhh = (const float*)d_in[7];
    const float* aw = (const float*)d_in[8];
    const float* ab = (const float*)d_in[9];
    const float* cw = (const float*)d_in[10];
    const float* cb = (const float*)d_in[11];
    const float* ow = (const float*)d_in[12];
    const float* obp = (const float*)d_in[13];
    const int* tpl = (const int*)d_in[14];
    const int* inp = (const int*)d_in[15];
    float* out = (float*)d_out;
    float* oidx = (out_size >= BB * ML * VS + BB * ML) ? out + (size_t)BB * ML * VS : nullptr;

    for (int s = 0; s < ML - 1; ++s) {
        k1_prep<<<BB, 512>>>(s, z, enc, tmo, emb, tpl, inp, out, oidx);
        k2_mm<<<48, 256>>>(wih, whh);
        k3_attn<<<BB, 256>>>(enc, bih, bhh, aw, ab, cw, cb, inp);
        k4_gen<<<NB4, 256>>>(ow, obp);
        k6_final<<<dim3(118, BB), 256>>>(s, out);
    }
}

// round 12
// speedup vs baseline: 3.1199x; 3.0525x over previous
#include <cuda_runtime.h>
#include <math.h>

#define BB 16
#define SS 100
#define VV 30000
#define HH 512
#define EE 300
#define TT 50
#define ML 50
#define DD 1836
#define VS 30100
#define NEGV (-1000000.0f)
#define NBK 118

__device__ float g_xT[(DD + HH) * BB];
__device__ float g_yT[1024 * BB];
__device__ float g_hidden[BB * HH];
__device__ float g_prehid[BB * HH];
__device__ float g_selread[BB * HH];
__device__ float g_css[BB * SS];
__device__ float g_cs[BB * VV];
__device__ float g_G[BB * VV];
__device__ float g_gi[BB * 1536];
__device__ float g_gh[BB * 1536];
__device__ float g_bmax[BB * NBK];
__device__ float g_bsum[BB * NBK];
__device__ unsigned long long g_amax[BB];
__device__ int g_presamp[BB], g_eos[BB], g_preseg[BB], g_index[BB], g_clen[BB];

__device__ __forceinline__ unsigned long long pk2(float lo, float hi) {
    unsigned long long r;
    asm("mov.b64 %0,{%1,%2};" : "=l"(r) : "f"(lo), "f"(hi));
    return r;
}
__device__ __forceinline__ void upk2(float& lo, float& hi, unsigned long long v) {
    asm("mov.b64 {%0,%1},%2;" : "=f"(lo), "=f"(hi) : "l"(v));
}
__device__ __forceinline__ void ffma2(unsigned long long& d, unsigned long long a,
                                      unsigned long long b) {
    asm("fma.rn.f32x2 %0,%1,%2,%0;" : "+l"(d) : "l"(a), "l"(b));
}
__device__ __forceinline__ void cpa16(void* dst, const void* src) {
    unsigned d = (unsigned)__cvta_generic_to_shared(dst);
    asm volatile("cp.async.cg.shared.global [%0],[%1],16;" ::"r"(d), "l"(src));
}

// control + selread + build x ; step 0 also does all per-launch init
__global__ __launch_bounds__(512) void k1_prep(int step, const float* __restrict__ z,
        const float* __restrict__ enc, const float* __restrict__ tmo,
        const float* __restrict__ emb, const int* __restrict__ tpl,
        const int* __restrict__ inp, float* __restrict__ out, float* __restrict__ oidx) {
    int b = blockIdx.x, tid = threadIdx.x;
    __shared__ float s_sel[SS];
    __shared__ float s_red[512];
    __shared__ int s_ctrl[3];

    if (step == 0) {
        float* orow = out + (size_t)b * ML * VS;
        for (int j = tid; j < VS; j += 512) orow[j] = (j == 1) ? 1.f : 0.f;
        for (int v = tid; v < VV; v += 512) g_cs[(size_t)b * VV + v] = NEGV;
        g_hidden[b * HH + tid] = z[b * HH + tid];
        g_prehid[b * HH + tid] = z[b * HH + tid];
        g_selread[b * HH + tid] = 0.f;
        if (tid == 0 && oidx) oidx[b * ML] = 1.f;
    }

    int samp = (step == 0) ? 1 : (0x7FFFFFFF - (int)(g_amax[b] & 0xFFFFFFFFull));
    if (step > 0) {
        if (tid < SS) s_sel[tid] = (inp[b * SS + tid] == samp) ? g_css[b * SS + tid] : 0.f;
        __syncthreads();
        s_red[tid] = (tid < SS) ? fabsf(s_sel[tid]) : 0.f;
        __syncthreads();
        for (int o = 256; o > 0; o >>= 1) {
            if (tid < o) s_red[tid] += s_red[tid + o];
            __syncthreads();
        }
        float inv = 1.f / fmaxf(s_red[0], 1e-12f);
        float acc = 0.f;
        const float* e = enc + (size_t)b * SS * HH + tid;
#pragma unroll 4
        for (int s = 0; s < SS; ++s) acc += s_sel[s] * e[(size_t)s * HH];
        g_selread[b * HH + tid] = acc * inv;
    }
    __syncthreads();
    if (tid == 0) {
        int ps, eos, preseg, index, clen;
        if (step == 0) { ps = 1; eos = 1; preseg = tpl[b * TT]; index = 0; clen = 0; }
        else { ps = g_presamp[b]; eos = g_eos[b]; preseg = g_preseg[b]; index = g_index[b]; clen = g_clen[b]; }
        int eos_new = (ps == 6) ? eos : ps;
        int flag = (preseg != 5) || (ps == 6) || (clen > 20);
        index += flag ? 1 : 0;
        clen += flag ? 0 : 1;
        int seg = tpl[b * TT + index];
        int sampled = flag ? seg : samp;
        if (oidx) oidx[b * ML + step + 1] = (float)sampled;
        int keep = (sampled == 5) || (sampled == 6);
        int s2 = (sampled == 6) ? eos_new : sampled;
        g_presamp[b] = sampled; g_eos[b] = eos_new; g_preseg[b] = seg;
        g_index[b] = index; g_clen[b] = clen;
        g_amax[b] = 0ull;
        s_ctrl[0] = index; s_ctrl[1] = keep; s_ctrl[2] = (s2 > VV) ? 3 : s2;
    }
    __syncthreads();
    int index = s_ctrl[0], keep = s_ctrl[1], ie = s_ctrl[2];
    float ph = keep ? g_prehid[b * HH + tid] : g_hidden[b * HH + tid];
    g_prehid[b * HH + tid] = ph;
    g_xT[tid * BB + b] = ph;
    g_xT[(HH + tid) * BB + b] = tmo[((size_t)b * TT + index) * HH + tid];
    g_xT[(2 * HH + tid) * BB + b] = g_selread[b * HH + tid];
    if (tid < EE) g_xT[(3 * HH + tid) * BB + b] = emb[(size_t)ie * EE + tid];
    g_xT[(DD + tid) * BB + b] = ph;
}

// GRU matvecs, reg-prefetch double buffered, conflict-free k-major y
__global__ __launch_bounds__(256) void k2_mm(const float* __restrict__ wih,
                                             const float* __restrict__ whh) {
    __shared__ float ws[64][68];
    __shared__ float ysc[64 * 16];
    int blk = blockIdx.x, tid = threadIdx.x;
    int ih = blk < 24;
    const float* W = ih ? wih : whh;
    int nk = ih ? DD : HH, koff = ih ? 0 : DD;
    int row0 = (ih ? blk : blk - 24) * 64;
    float* outp = ih ? g_gi : g_gh;
    int ty = tid >> 2, tx = tid & 3;
    unsigned long long aA = 0, aB = 0;
    int nc = (nk + 63) >> 6;

    float4 wreg[4], yreg;
    {
        for (int i = 0; i < 4; ++i) {
            int l = tid + i * 256, r = l >> 4, kq = (l & 15) * 4;
            wreg[i] = (kq + 3 < nk) ? *(const float4*)&W[(size_t)(row0 + r) * nk + kq]
                                    : make_float4(0.f, 0.f, 0.f, 0.f);
        }
        yreg = ((tid >> 2) < nk) ? *(const float4*)&g_xT[koff * BB + tid * 4]
                                 : make_float4(0.f, 0.f, 0.f, 0.f);
    }
    for (int c = 0; c < nc; ++c) {
        for (int i = 0; i < 4; ++i) {
            int l = tid + i * 256, r = l >> 4, kq = (l & 15) * 4;
            *(float4*)&ws[r][kq] = wreg[i];
        }
        *(float4*)&ysc[tid * 4] = yreg;
        __syncthreads();
        if (c + 1 < nc) {
            int k0 = (c + 1) * 64;
            for (int i = 0; i < 4; ++i) {
                int l = tid + i * 256, r = l >> 4, kq = (l & 15) * 4;
                wreg[i] = (k0 + kq + 3 < nk) ? *(const float4*)&W[(size_t)(row0 + r) * nk + k0 + kq]
                                             : make_float4(0.f, 0.f, 0.f, 0.f);
            }
            yreg = (k0 + (tid >> 2) < nk) ? *(const float4*)&g_xT[(koff + k0) * BB + tid * 4]
                                          : make_float4(0.f, 0.f, 0.f, 0.f);
        }
#pragma unroll
        for (int kk = 0; kk < 64; kk += 4) {
            float4 w = *(float4*)&ws[ty][kk];
            unsigned long long ya0 = *(unsigned long long*)&ysc[(kk + 0) * 16 + 2 * tx];
            unsigned long long ya1 = *(unsigned long long*)&ysc[(kk + 1) * 16 + 2 * tx];
            unsigned long long ya2 = *(unsigned long long*)&ysc[(kk + 2) * 16 + 2 * tx];
            unsigned long long ya3 = *(unsigned long long*)&ysc[(kk + 3) * 16 + 2 * tx];
            unsigned long long yb0 = *(unsigned long long*)&ysc[(kk + 0) * 16 + 2 * (tx + 4)];
            unsigned long long yb1 = *(unsigned long long*)&ysc[(kk + 1) * 16 + 2 * (tx + 4)];
            unsigned long long yb2 = *(unsigned long long*)&ysc[(kk + 2) * 16 + 2 * (tx + 4)];
            unsigned long long yb3 = *(unsigned long long*)&ysc[(kk + 3) * 16 + 2 * (tx + 4)];
            unsigned long long p;
            p = pk2(w.x, w.x); ffma2(aA, p, ya0); ffma2(aB, p, yb0);
            p = pk2(w.y, w.y); ffma2(aA, p, ya1); ffma2(aB, p, yb1);
            p = pk2(w.z, w.z); ffma2(aA, p, ya2); ffma2(aB, p, yb2);
            p = pk2(w.w, w.w); ffma2(aA, p, ya3); ffma2(aB, p, yb3);
        }
        __syncthreads();
    }
    float f0, f1, f2, f3;
    upk2(f0, f1, aA); upk2(f2, f3, aB);
    int r = row0 + ty;
    outp[(2 * tx) * 1536 + r] = f0;
    outp[(2 * tx + 1) * 1536 + r] = f1;
    outp[(2 * tx + 8) * 1536 + r] = f2;
    outp[(2 * tx + 9) * 1536 + r] = f3;
}

// fused GRU gates + attention + copy scores
__global__ __launch_bounds__(256) void k3_attn(const float* __restrict__ enc,
        const float* __restrict__ bi, const float* __restrict__ bh,
        const float* __restrict__ aw, const float* __restrict__ ab,
        const float* __restrict__ cw, const float* __restrict__ cb,
        const int* __restrict__ inp) {
    int b = blockIdx.x, tid = threadIdx.x;
    __shared__ float s_hid[HH], s_th[HH], s_th2[HH], s_sc[SS], s_css[SS];
    __shared__ int s_inp[SS];
    int o = b * 1536;
    for (int h = tid; h < HH; h += 256) {
        float r = 1.f / (1.f + expf(-(g_gi[o + h] + bi[h] + g_gh[o + h] + bh[h])));
        float zg = 1.f / (1.f + expf(-(g_gi[o + 512 + h] + bi[512 + h] + g_gh[o + 512 + h] + bh[512 + h])));
        float n = tanhf(g_gi[o + 1024 + h] + bi[1024 + h] + r * (g_gh[o + 1024 + h] + bh[1024 + h]));
        float hp = g_prehid[b * HH + h];
        float hn = (1.f - zg) * n + zg * hp;
        g_hidden[b * HH + h] = hn;
        g_yT[(512 + h) * BB + b] = hn;
        s_hid[h] = hn;
    }
    if (tid < SS) s_inp[tid] = inp[b * SS + tid];
    __syncthreads();
    for (int i = tid; i < HH; i += 256) {
        float a = 0.f, c = 0.f;
        const float* wa = aw + (size_t)i * HH;
        const float* wc = cw + (size_t)i * HH;
#pragma unroll 4
        for (int k = 0; k < HH; k += 4) {
            float4 w1 = *(const float4*)&wa[k];
            float4 w2 = *(const float4*)&wc[k];
            a += w1.x * s_hid[k] + w1.y * s_hid[k + 1] + w1.z * s_hid[k + 2] + w1.w * s_hid[k + 3];
            c += w2.x * s_hid[k] + w2.y * s_hid[k + 1] + w2.z * s_hid[k + 2] + w2.w * s_hid[k + 3];
        }
        s_th[i] = a + ab[i];
        s_th2[i] = c + cb[i];
    }
    __syncthreads();
    int wid = tid >> 5, lane = tid & 31;
    for (int s = wid; s < SS; s += 8) {
        const float* e = enc + ((size_t)b * SS + s) * HH;
        float a = 0.f, c = 0.f;
        for (int k = lane; k < HH; k += 32) {
            float ev = e[k];
            a += ev * s_th[k];
            c += ev * s_th2[k];
        }
        for (int off = 16; off > 0; off >>= 1) {
            a += __shfl_down_sync(0xffffffffu, a, off);
            c += __shfl_down_sync(0xffffffffu, c, off);
        }
        if (lane == 0) { s_sc[s] = a; s_css[s] = c; }
    }
    __syncthreads();
    if (wid == 0) {
        float m = -3.4e38f;
        for (int s = lane; s < SS; s += 32) m = fmaxf(m, s_sc[s]);
        for (int off = 16; off > 0; off >>= 1) m = fmaxf(m, __shfl_xor_sync(0xffffffffu, m, off));
        float sum = 0.f;
        for (int s = lane; s < SS; s += 32) {
            float e = expf(s_sc[s] - m);
            s_sc[s] = e; sum += e;
        }
        for (int off = 16; off > 0; off >>= 1) sum += __shfl_xor_sync(0xffffffffu, sum, off);
        float inv = 1.f / sum;
        for (int s = lane; s < SS; s += 32) s_sc[s] *= inv;
    }
    __syncthreads();
    for (int h = tid; h < HH; h += 256) {
        float acc = 0.f;
        const float* e = enc + (size_t)b * SS * HH + h;
#pragma unroll 4
        for (int s = 0; s < SS; ++s) acc += s_sc[s] * e[(size_t)s * HH];
        g_yT[h * BB + b] = acc;
    }
    if (tid < SS) g_css[b * SS + tid] = s_css[tid];
    for (int s = tid; s < SS; s += 256) {
        int t = s_inp[s];
        if (t != 0) {
            float sum = 0.f;
            for (int s2 = 0; s2 < SS; ++s2)
                if (s_inp[s2] == t) sum += s_css[s2];
            g_cs[(size_t)b * VV + t] = sum;
        }
    }
}

// gen GEMM: 256-row tiles, cp.async double-buffered weights, y resident in smem
__global__ __launch_bounds__(256) void k4_gen(const float* __restrict__ ow,
                                              const float* __restrict__ ob) {
    extern __shared__ float sm[];
    float* ys = sm;              // 16384 floats (all y, k-major [k][16])
    float* ws = sm + 16384;      // 2 stages x 256 rows x 36
    float* s_m = ws + 2 * 9216;  // [16][64]
    float* s_s = s_m + 1024;     // [16][64]
    int blk = blockIdx.x, tid = threadIdx.x;
    int v0 = blk * 256;
    int ty = tid >> 2, tx = tid & 3;
    int prow = tid >> 3, pcol = tid & 7;

    // prefetch chunk 0
    for (int i = 0; i < 8; ++i) {
        int r = prow + i * 32;
        if (v0 + r < VV)
            cpa16(&ws[r * 36 + pcol * 4], &ow[(size_t)(v0 + r) * 1024 + pcol * 4]);
    }
    asm volatile("cp.async.commit_group;");
    // load all y (layout-identical flat copy)
    for (int i = 0; i < 16; ++i) {
        int idx = (tid + i * 256) * 4;
        *(float4*)&ys[idx] = *(const float4*)&g_yT[idx];
    }
    unsigned long long acc[4][2];
#pragma unroll
    for (int j = 0; j < 4; ++j) { acc[j][0] = 0ull; acc[j][1] = 0ull; }

    for (int c = 0; c < 32; ++c) {
        if (c + 1 < 32) {
            int kc2 = (c + 1) * 32, s2 = (c + 1) & 1;
            for (int i = 0; i < 8; ++i) {
                int r = prow + i * 32;
                if (v0 + r < VV)
                    cpa16(&ws[s2 * 9216 + r * 36 + pcol * 4],
                          &ow[(size_t)(v0 + r) * 1024 + kc2 + pcol * 4]);
            }
            asm volatile("cp.async.commit_group;");
            asm volatile("cp.async.wait_group 1;");
        } else {
            asm volatile("cp.async.wait_group 0;");
        }
        __syncthreads();
        int kc = c * 32;
        const float* wb = &ws[(c & 1) * 9216];
#pragma unroll
        for (int kk = 0; kk < 32; kk += 4) {
            unsigned long long ya0 = *(unsigned long long*)&ys[(kc + kk + 0) * 16 + 2 * tx];
            unsigned long long ya1 = *(unsigned long long*)&ys[(kc + kk + 1) * 16 + 2 * tx];
            unsigned long long ya2 = *(unsigned long long*)&ys[(kc + kk + 2) * 16 + 2 * tx];
            unsigned long long ya3 = *(unsigned long long*)&ys[(kc + kk + 3) * 16 + 2 * tx];
            unsigned long long yb0 = *(unsigned long long*)&ys[(kc + kk + 0) * 16 + 2 * (tx + 4)];
            unsigned long long yb1 = *(unsigned long long*)&ys[(kc + kk + 1) * 16 + 2 * (tx + 4)];
            unsigned long long yb2 = *(unsigned long long*)&ys[(kc + kk + 2) * 16 + 2 * (tx + 4)];
            unsigned long long yb3 = *(unsigned long long*)&ys[(kc + kk + 3) * 16 + 2 * (tx + 4)];
#pragma unroll
            for (int j = 0; j < 4; ++j) {
                float4 w = *(const float4*)&wb[(ty + 64 * j) * 36 + kk];
                unsigned long long p;
                p = pk2(w.x, w.x); ffma2(acc[j][0], p, ya0); ffma2(acc[j][1], p, yb0);
                p = pk2(w.y, w.y); ffma2(acc[j][0], p, ya1); ffma2(acc[j][1], p, yb1);
                p = pk2(w.z, w.z); ffma2(acc[j][0], p, ya2); ffma2(acc[j][1], p, yb2);
                p = pk2(w.w, w.w); ffma2(acc[j][0], p, ya3); ffma2(acc[j][1], p, yb3);
            }
        }
        __syncthreads();
    }

    int bs[4] = {2 * tx, 2 * tx + 1, 2 * tx + 8, 2 * tx + 9};
    float mloc[4] = {-3.4e38f, -3.4e38f, -3.4e38f, -3.4e38f};
    float sloc[4] = {0.f, 0.f, 0.f, 0.f};
#pragma unroll
    for (int j = 0; j < 4; ++j) {
        int row = v0 + ty + 64 * j;
        bool val = row < VV;
        float obv = val ? ob[row] : 0.f;
        float g[4];
        upk2(g[0], g[1], acc[j][0]); upk2(g[2], g[3], acc[j][1]);
#pragma unroll
        for (int q = 0; q < 4; ++q) {
            float gg = g[q] + obv;
            if (!val || row == 0) gg = NEGV;
            float cc;
            if (val) {
                g_G[(size_t)bs[q] * VV + row] = gg;
                cc = g_cs[(size_t)bs[q] * VV + row];
            } else cc = NEGV;
            float m = fmaxf(gg, cc);
            float nm = fmaxf(mloc[q], m);
            sloc[q] = sloc[q] * expf(mloc[q] - nm) + expf(gg - nm) + expf(cc - nm);
            mloc[q] = nm;
        }
    }
#pragma unroll
    for (int q = 0; q < 4; ++q) {
        s_m[bs[q] * 64 + ty] = mloc[q];
        s_s[bs[q] * 64 + ty] = sloc[q];
    }
    __syncthreads();
    if (tid < 16) {
        float M = -3.4e38f;
        for (int t = 0; t < 64; ++t) M = fmaxf(M, s_m[tid * 64 + t]);
        float S = 0.f;
        for (int t = 0; t < 64; ++t) S += s_s[tid * 64 + t] * expf(s_m[tid * 64 + t] - M);
        g_bmax[tid * NBK + blk] = M;
        g_bsum[tid * NBK + blk] = S;
    }
}

// softmax combine + final probs + argmax
__global__ __launch_bounds__(256) void k6_final(int step, float* __restrict__ out) {
    __shared__ float s_red[256];
    __shared__ unsigned long long s_k[256];
    __shared__ float s_M, s_Zi;
    int b = blockIdx.y, tid = threadIdx.x;
    float lm = -3.4e38f;
    for (int i = tid; i < NBK; i += 256) lm = fmaxf(lm, g_bmax[b * NBK + i]);
    s_red[tid] = lm; __syncthreads();
    for (int o = 128; o > 0; o >>= 1) {
        if (tid < o) s_red[tid] = fmaxf(s_red[tid], s_red[tid + o]);
        __syncthreads();
    }
    if (tid == 0) s_M = s_red[0];
    __syncthreads();
    float M = s_M;
    float ls = 0.f;
    for (int i = tid; i < NBK; i += 256) ls += g_bsum[b * NBK + i] * expf(g_bmax[b * NBK + i] - M);
    s_red[tid] = ls; __syncthreads();
    for (int o = 128; o > 0; o >>= 1) {
        if (tid < o) s_red[tid] += s_red[tid + o];
        __syncthreads();
    }
    if (tid == 0) s_Zi = 1.f / s_red[0];
    __syncthreads();
    float Zi = s_Zi;

    int v = blockIdx.x * 256 + tid;
    float* orow = out + ((size_t)b * ML + step + 1) * VS;
    unsigned long long key = 0ull;
    if (v < VV) {
        float f = (expf(g_G[(size_t)b * VV + v] - M) + expf(g_cs[(size_t)b * VV + v] - M)) * Zi;
        orow[v] = f;
        unsigned int u = __float_as_uint(f);
        unsigned int mono = u ^ ((u >> 31) ? 0xFFFFFFFFu : 0x80000000u);
        key = ((unsigned long long)mono << 32) | (unsigned int)(0x7FFFFFFF - v);
    } else if (v < VS) {
        orow[v] = 0.f;
    }
    s_k[tid] = key;
    __syncthreads();
    for (int o = 128; o > 0; o >>= 1) {
        if (tid < o) s_k[tid] = max(s_k[tid], s_k[tid + o]);
        __syncthreads();
    }
    if (tid == 0 && s_k[0]) atomicMax(&g_amax[b], s_k[0]);
}

extern "C" void kernel_launch(void* const* d_in, const int* in_sizes, int n_in,
                              void* d_out, int out_size) {
    const float* enc = (const float*)d_in[0];
    const float* tmo = (const float*)d_in[1];
    const float* z = (const float*)d_in[2];
    const float* emb = (const float*)d_in[3];
    const float* wih = (const float*)d_in[4];
    const float* whh = (const float*)d_in[5];
    const float* bih = (const float*)d_in[6];
    const float* bhh = (const float*)d_in[7];
    const float* aw = (const float*)d_in[8];
    const float* ab = (const float*)d_in[9];
    const float* cw = (const float*)d_in[10];
    const float* cb = (const float*)d_in[11];
    const float* ow = (const float*)d_in[12];
    const float* obp = (const float*)d_in[13];
    const int* tpl = (const int*)d_in[14];
    const int* inp = (const int*)d_in[15];
    float* out = (float*)d_out;
    float* oidx = (out_size >= BB * ML * VS + BB * ML) ? out + (size_t)BB * ML * VS : nullptr;

    const int k4smem = (16384 + 2 * 9216 + 2 * 1024) * 4;  // 147456 B
    cudaFuncSetAttribute((const void*)k4_gen, cudaFuncAttributeMaxDynamicSharedMemorySize, k4smem);

    for (int s = 0; s < ML - 1; ++s) {
        k1_prep<<<BB, 512>>>(s, z, enc, tmo, emb, tpl, inp, out, oidx);
        k2_mm<<<48, 256>>>(wih, whh);
        k3_attn<<<BB, 256>>>(enc, bih, bhh, aw, ab, cw, cb, inp);
        k4_gen<<<NBK, 256, k4smem>>>(ow, obp);
        k6_final<<<dim3(118, BB), 256>>>(s, out);
    }
}

// round 15
// speedup vs baseline: 4.0748x; 1.3061x over previous
#include <cuda_runtime.h>
#include <math.h>

#define BB 16
#define SS 100
#define VV 30000
#define HH 512
#define EE 300
#define TT 50
#define ML 50
#define DD 1836
#define VS 30100
#define NEGV (-1000000.0f)
#define NBK 118

__device__ float g_xT[(DD + HH) * BB];
__device__ float g_yT[1024 * BB];
__device__ float g_hidden[BB * HH];
__device__ float g_prehid[BB * HH];
__device__ float g_selread[BB * HH];
__device__ float g_css[BB * SS];
__device__ float g_cs[BB * VV];
__device__ float g_G[BB * VV];
__device__ float g_gi[BB * 1536];
__device__ float g_gh[BB * 1536];
__device__ float g_bmax[BB * NBK];
__device__ float g_bsum[BB * NBK];
__device__ float g_Ea[BB * SS * HH];
__device__ float g_Ec[BB * SS * HH];
__device__ float g_ca[BB * SS];
__device__ float g_cc[BB * SS];
__device__ unsigned long long g_amax[BB];
__device__ int g_presamp[BB], g_eos[BB], g_preseg[BB], g_index[BB], g_clen[BB];

__device__ __forceinline__ unsigned long long pk2(float lo, float hi) {
    unsigned long long r;
    asm("mov.b64 %0,{%1,%2};" : "=l"(r) : "f"(lo), "f"(hi));
    return r;
}
__device__ __forceinline__ void upk2(float& lo, float& hi, unsigned long long v) {
    asm("mov.b64 {%0,%1},%2;" : "=f"(lo), "=f"(hi) : "l"(v));
}
__device__ __forceinline__ void ffma2(unsigned long long& d, unsigned long long a,
                                      unsigned long long b) {
    asm("fma.rn.f32x2 %0,%1,%2,%0;" : "+l"(d) : "l"(a), "l"(b));
}
__device__ __forceinline__ void cpa16(void* dst, const void* src) {
    unsigned d = (unsigned)__cvta_generic_to_shared(dst);
    asm volatile("cp.async.cg.shared.global [%0],[%1],16;" ::"r"(d), "l"(src));
}

// ---- one-time: Ea = enc@aw, Ec = enc@cw, bias dots ----
__global__ __launch_bounds__(256) void k3pre(const float* __restrict__ enc,
        const float* __restrict__ aw, const float* __restrict__ ab,
        const float* __restrict__ cw, const float* __restrict__ cb) {
    __shared__ float s_e[104][64];
    __shared__ float s_aw[64][32];
    __shared__ float s_cw[64][32];
    int b = blockIdx.y, tid = threadIdx.x;
    int c0 = blockIdx.x * 32;
    int tx = tid & 31, sy = tid >> 5;
    float aa[13], cc2[13];
#pragma unroll
    for (int q = 0; q < 13; ++q) { aa[q] = 0.f; cc2[q] = 0.f; }

    for (int i0 = 0; i0 < 512; i0 += 64) {
        for (int j = 0; j < 26; ++j) {
            int l = tid + j * 256, s = l >> 6, io = l & 63;
            s_e[s][io] = (s < SS) ? enc[((size_t)b * SS + s) * HH + i0 + io] : 0.f;
        }
        for (int j = 0; j < 8; ++j) {
            int l = tid + j * 256, il = l >> 5, cl = l & 31;
            s_aw[il][cl] = aw[(size_t)(i0 + il) * HH + c0 + cl];
            s_cw[il][cl] = cw[(size_t)(i0 + il) * HH + c0 + cl];
        }
        __syncthreads();
        for (int i = 0; i < 64; ++i) {
            float awv = s_aw[i][tx], cwv = s_cw[i][tx];
#pragma unroll
            for (int q = 0; q < 13; ++q) {
                float ev = s_e[sy + q * 8][i];
                aa[q] += ev * awv;
                cc2[q] += ev * cwv;
            }
        }
        __syncthreads();
    }
#pragma unroll
    for (int q = 0; q < 13; ++q) {
        int s = sy + q * 8;
        if (s < SS) {
            g_Ea[((size_t)b * SS + s) * HH + c0 + tx] = aa[q];
            g_Ec[((size_t)b * SS + s) * HH + c0 + tx] = cc2[q];
        }
    }
    if (blockIdx.x == 0) {
        for (int s = sy; s < SS; s += 8) {
            const float* er = enc + ((size_t)b * SS + s) * HH;
            float pa = 0.f, pc = 0.f;
            for (int i = tx; i < HH; i += 32) {
                pa += er[i] * ab[i];
                pc += er[i] * cb[i];
            }
            for (int o = 16; o > 0; o >>= 1) {
                pa += __shfl_down_sync(0xffffffffu, pa, o);
                pc += __shfl_down_sync(0xffffffffu, pc, o);
            }
            if (tx == 0) { g_ca[b * SS + s] = pa; g_cc[b * SS + s] = pc; }
        }
    }
}

// control + selread + build x ; step 0 also does all per-launch init
__global__ __launch_bounds__(512) void k1_prep(int step, const float* __restrict__ z,
        const float* __restrict__ enc, const float* __restrict__ tmo,
        const float* __restrict__ emb, const int* __restrict__ tpl,
        const int* __restrict__ inp, float* __restrict__ out, float* __restrict__ oidx) {
    int b = blockIdx.x, tid = threadIdx.x;
    __shared__ float s_sel[SS];
    __shared__ float s_red[512];
    __shared__ int s_ctrl[3];

    if (step == 0) {
        float* orow = out + (size_t)b * ML * VS;
        for (int j = tid; j < VS; j += 512) orow[j] = (j == 1) ? 1.f : 0.f;
        for (int v = tid; v < VV; v += 512) g_cs[(size_t)b * VV + v] = NEGV;
        g_hidden[b * HH + tid] = z[b * HH + tid];
        g_prehid[b * HH + tid] = z[b * HH + tid];
        g_selread[b * HH + tid] = 0.f;
        if (tid == 0 && oidx) oidx[b * ML] = 1.f;
    }

    int samp = (step == 0) ? 1 : (0x7FFFFFFF - (int)(g_amax[b] & 0xFFFFFFFFull));
    if (step > 0) {
        if (tid < SS) s_sel[tid] = (inp[b * SS + tid] == samp) ? g_css[b * SS + tid] : 0.f;
        __syncthreads();
        s_red[tid] = (tid < SS) ? fabsf(s_sel[tid]) : 0.f;
        __syncthreads();
        for (int o = 256; o > 0; o >>= 1) {
            if (tid < o) s_red[tid] += s_red[tid + o];
            __syncthreads();
        }
        float inv = 1.f / fmaxf(s_red[0], 1e-12f);
        float acc = 0.f;
        const float* e = enc + (size_t)b * SS * HH + tid;
#pragma unroll 4
        for (int s = 0; s < SS; ++s) acc += s_sel[s] * e[(size_t)s * HH];
        g_selread[b * HH + tid] = acc * inv;
    }
    __syncthreads();
    if (tid == 0) {
        int ps, eos, preseg, index, clen;
        if (step == 0) { ps = 1; eos = 1; preseg = tpl[b * TT]; index = 0; clen = 0; }
        else { ps = g_presamp[b]; eos = g_eos[b]; preseg = g_preseg[b]; index = g_index[b]; clen = g_clen[b]; }
        int eos_new = (ps == 6) ? eos : ps;
        int flag = (preseg != 5) || (ps == 6) || (clen > 20);
        index += flag ? 1 : 0;
        clen += flag ? 0 : 1;
        int seg = tpl[b * TT + index];
        int sampled = flag ? seg : samp;
        if (oidx) oidx[b * ML + step + 1] = (float)sampled;
        int keep = (sampled == 5) || (sampled == 6);
        int s2 = (sampled == 6) ? eos_new : sampled;
        g_presamp[b] = sampled; g_eos[b] = eos_new; g_preseg[b] = seg;
        g_index[b] = index; g_clen[b] = clen;
        g_amax[b] = 0ull;
        s_ctrl[0] = index; s_ctrl[1] = keep; s_ctrl[2] = (s2 > VV) ? 3 : s2;
    }
    __syncthreads();
    int index = s_ctrl[0], keep = s_ctrl[1], ie = s_ctrl[2];
    float ph = keep ? g_prehid[b * HH + tid] : g_hidden[b * HH + tid];
    g_prehid[b * HH + tid] = ph;
    g_xT[tid * BB + b] = ph;
    g_xT[(HH + tid) * BB + b] = tmo[((size_t)b * TT + index) * HH + tid];
    g_xT[(2 * HH + tid) * BB + b] = g_selread[b * HH + tid];
    if (tid < EE) g_xT[(3 * HH + tid) * BB + b] = emb[(size_t)ie * EE + tid];
    g_xT[(DD + tid) * BB + b] = ph;
}

// GRU matvecs: 96 blocks x 32 rows (48 ih + 48 hh), 8 batch-pairs, reg double-buffer
__global__ __launch_bounds__(256) void k2_mm(const float* __restrict__ wih,
                                             const float* __restrict__ whh) {
    __shared__ float ws[32][68];
    __shared__ float ysc[64 * 16];
    int blk = blockIdx.x, tid = threadIdx.x;
    int ih = blk < 48;
    const float* W = ih ? wih : whh;
    int nk = ih ? DD : HH, koff = ih ? 0 : DD;
    int row0 = (ih ? blk : blk - 48) * 32;
    float* outp = ih ? g_gi : g_gh;
    int ty = tid >> 3, tx = tid & 7;
    unsigned long long acc = 0ull;
    int nc = (nk + 63) >> 6;

    float4 wreg[2], yreg;
    for (int i = 0; i < 2; ++i) {
        int l = tid + i * 256, r = l >> 4, kq = (l & 15) * 4;
        wreg[i] = (kq + 3 < nk) ? *(const float4*)&W[(size_t)(row0 + r) * nk + kq]
                                : make_float4(0.f, 0.f, 0.f, 0.f);
    }
    yreg = ((tid >> 2) < nk) ? *(const float4*)&g_xT[koff * BB + tid * 4]
                             : make_float4(0.f, 0.f, 0.f, 0.f);

    for (int c = 0; c < nc; ++c) {
        for (int i = 0; i < 2; ++i) {
            int l = tid + i * 256, r = l >> 4, kq = (l & 15) * 4;
            *(float4*)&ws[r][kq] = wreg[i];
        }
        *(float4*)&ysc[tid * 4] = yreg;
        __syncthreads();
        if (c + 1 < nc) {
            int k0 = (c + 1) * 64;
            for (int i = 0; i < 2; ++i) {
                int l = tid + i * 256, r = l >> 4, kq = (l & 15) * 4;
                wreg[i] = (k0 + kq + 3 < nk) ? *(const float4*)&W[(size_t)(row0 + r) * nk + k0 + kq]
                                             : make_float4(0.f, 0.f, 0.f, 0.f);
            }
            yreg = (k0 + (tid >> 2) < nk) ? *(const float4*)&g_xT[(koff + k0) * BB + tid * 4]
                                          : make_float4(0.f, 0.f, 0.f, 0.f);
        }
#pragma unroll
        for (int kk = 0; kk < 64; kk += 4) {
            float4 w = *(float4*)&ws[ty][kk];
            unsigned long long y0 = *(unsigned long long*)&ysc[(kk + 0) * 16 + 2 * tx];
            unsigned long long y1 = *(unsigned long long*)&ysc[(kk + 1) * 16 + 2 * tx];
            unsigned long long y2 = *(unsigned long long*)&ysc[(kk + 2) * 16 + 2 * tx];
            unsigned long long y3 = *(unsigned long long*)&ysc[(kk + 3) * 16 + 2 * tx];
            ffma2(acc, pk2(w.x, w.x), y0);
            ffma2(acc, pk2(w.y, w.y), y1);
            ffma2(acc, pk2(w.z, w.z), y2);
            ffma2(acc, pk2(w.w, w.w), y3);
        }
        __syncthreads();
    }
    float f0, f1;
    upk2(f0, f1, acc);
    int r = row0 + ty;
    outp[(2 * tx) * 1536 + r] = f0;
    outp[(2 * tx + 1) * 1536 + r] = f1;
}

// gates + attention via precomputed Ea/Ec + copy scatter
__global__ __launch_bounds__(256) void k3_attn(const float* __restrict__ enc,
        const float* __restrict__ bi, const float* __restrict__ bh,
        const int* __restrict__ inp) {
    int b = blockIdx.x, tid = threadIdx.x;
    __shared__ float s_hid[HH], s_sc[SS], s_css[SS];
    __shared__ int s_inp[SS];
    int o = b * 1536;
    for (int h = tid; h < HH; h += 256) {
        float r = 1.f / (1.f + expf(-(g_gi[o + h] + bi[h] + g_gh[o + h] + bh[h])));
        float zg = 1.f / (1.f + expf(-(g_gi[o + 512 + h] + bi[512 + h] + g_gh[o + 512 + h] + bh[512 + h])));
        float n = tanhf(g_gi[o + 1024 + h] + bi[1024 + h] + r * (g_gh[o + 1024 + h] + bh[1024 + h]));
        float hp = g_prehid[b * HH + h];
        float hn = (1.f - zg) * n + zg * hp;
        g_hidden[b * HH + h] = hn;
        g_yT[(512 + h) * BB + b] = hn;
        s_hid[h] = hn;
    }
    if (tid < SS) s_inp[tid] = inp[b * SS + tid];
    __syncthreads();
    int wid = tid >> 5, lane = tid & 31;
    for (int s = wid; s < SS; s += 8) {
        const float* ea = g_Ea + ((size_t)b * SS + s) * HH;
        const float* ec = g_Ec + ((size_t)b * SS + s) * HH;
        float a = 0.f, c = 0.f;
        for (int k = lane; k < HH; k += 32) {
            float hv = s_hid[k];
            a += ea[k] * hv;
            c += ec[k] * hv;
        }
        for (int off = 16; off > 0; off >>= 1) {
            a += __shfl_down_sync(0xffffffffu, a, off);
            c += __shfl_down_sync(0xffffffffu, c, off);
        }
        if (lane == 0) {
            s_sc[s] = a + g_ca[b * SS + s];
            s_css[s] = c + g_cc[b * SS + s];
        }
    }
    __syncthreads();
    if (wid == 0) {
        float m = -3.4e38f;
        for (int s = lane; s < SS; s += 32) m = fmaxf(m, s_sc[s]);
        for (int off = 16; off > 0; off >>= 1) m = fmaxf(m, __shfl_xor_sync(0xffffffffu, m, off));
        float sum = 0.f;
        for (int s = lane; s < SS; s += 32) {
            float e = expf(s_sc[s] - m);
            s_sc[s] = e; sum += e;
        }
        for (int off = 16; off > 0; off >>= 1) sum += __shfl_xor_sync(0xffffffffu, sum, off);
        float inv = 1.f / sum;
        for (int s = lane; s < SS; s += 32) s_sc[s] *= inv;
    }
    __syncthreads();
    for (int h = tid; h < HH; h += 256) {
        float acc = 0.f;
        const float* e = enc + (size_t)b * SS * HH + h;
#pragma unroll 4
        for (int s = 0; s < SS; ++s) acc += s_sc[s] * e[(size_t)s * HH];
        g_yT[h * BB + b] = acc;
    }
    if (tid < SS) g_css[b * SS + tid] = s_css[tid];
    for (int s = tid; s < SS; s += 256) {
        int t = s_inp[s];
        if (t != 0) {
            float sum = 0.f;
            for (int s2 = 0; s2 < SS; ++s2)
                if (s_inp[s2] == t) sum += s_css[s2];
            g_cs[(size_t)b * VV + t] = sum;
        }
    }
}

// gen GEMM: 512 threads, 3-stage cp.async, 2 rows x 4 batches per thread
__global__ __launch_bounds__(512) void k4_gen(const float* __restrict__ ow,
                                              const float* __restrict__ ob) {
    extern __shared__ float sm[];
    float* ys = sm;               // 16384 floats
    float* ws = sm + 16384;       // 3 x 9216
    float* s_m = ws;              // reused after compute: [16][128]
    float* s_s = ws + 2048;
    int blk = blockIdx.x, tid = threadIdx.x;
    int v0 = blk * 256;
    int ty = tid >> 2, tx = tid & 3;
    int prow = tid >> 3, pcol = tid & 7;

    for (int c0 = 0; c0 < 2; ++c0) {
        for (int i = 0; i < 4; ++i) {
            int r = prow + i * 64;
            if (v0 + r < VV)
                cpa16(&ws[c0 * 9216 + r * 36 + pcol * 4],
                      &ow[(size_t)(v0 + r) * 1024 + c0 * 32 + pcol * 4]);
        }
        asm volatile("cp.async.commit_group;");
    }
    for (int i = 0; i < 8; ++i) {
        int idx = (tid + i * 512) * 4;
        *(float4*)&ys[idx] = *(const float4*)&g_yT[idx];
    }
    unsigned long long acc[2][2];
    acc[0][0] = acc[0][1] = acc[1][0] = acc[1][1] = 0ull;

    for (int c = 0; c < 32; ++c) {
        if (c + 2 < 32) {
            int st = (c + 2) % 3, kc2 = (c + 2) * 32;
            for (int i = 0; i < 4; ++i) {
                int r = prow + i * 64;
                if (v0 + r < VV)
                    cpa16(&ws[st * 9216 + r * 36 + pcol * 4],
                          &ow[(size_t)(v0 + r) * 1024 + kc2 + pcol * 4]);
            }
            asm volatile("cp.async.commit_group;");
        }
        if (c <= 29) asm volatile("cp.async.wait_group 2;");
        else if (c == 30) asm volatile("cp.async.wait_group 1;");
        else asm volatile("cp.async.wait_group 0;");
        __syncthreads();
        int kc = c * 32;
        const float* wb = &ws[(c % 3) * 9216];
#pragma unroll
        for (int kk = 0; kk < 32; kk += 4) {
            unsigned long long ya0 = *(unsigned long long*)&ys[(kc + kk + 0) * 16 + 2 * tx];
            unsigned long long ya1 = *(unsigned long long*)&ys[(kc + kk + 1) * 16 + 2 * tx];
            unsigned long long ya2 = *(unsigned long long*)&ys[(kc + kk + 2) * 16 + 2 * tx];
            unsigned long long ya3 = *(unsigned long long*)&ys[(kc + kk + 3) * 16 + 2 * tx];
            unsigned long long yb0 = *(unsigned long long*)&ys[(kc + kk + 0) * 16 + 2 * (tx + 4)];
            unsigned long long yb1 = *(unsigned long long*)&ys[(kc + kk + 1) * 16 + 2 * (tx + 4)];
            unsigned long long yb2 = *(unsigned long long*)&ys[(kc + kk + 2) * 16 + 2 * (tx + 4)];
            unsigned long long yb3 = *(unsigned long long*)&ys[(kc + kk + 3) * 16 + 2 * (tx + 4)];
#pragma unroll
            for (int j = 0; j < 2; ++j) {
                float4 w = *(const float4*)&wb[(ty + 128 * j) * 36 + kk];
                unsigned long long p;
                p = pk2(w.x, w.x); ffma2(acc[j][0], p, ya0); ffma2(acc[j][1], p, yb0);
                p = pk2(w.y, w.y); ffma2(acc[j][0], p, ya1); ffma2(acc[j][1], p, yb1);
                p = pk2(w.z, w.z); ffma2(acc[j][0], p, ya2); ffma2(acc[j][1], p, yb2);
                p = pk2(w.w, w.w); ffma2(acc[j][0], p, ya3); ffma2(acc[j][1], p, yb3);
            }
        }
        __syncthreads();
    }

    int bs[4] = {2 * tx, 2 * tx + 1, 2 * tx + 8, 2 * tx + 9};
    float mloc[4] = {-3.4e38f, -3.4e38f, -3.4e38f, -3.4e38f};
    float sloc[4] = {0.f, 0.f, 0.f, 0.f};
#pragma unroll
    for (int j = 0; j < 2; ++j) {
        int row = v0 + ty + 128 * j;
        bool val = row < VV;
        float obv = val ? ob[row] : 0.f;
        float g[4];
        upk2(g[0], g[1], acc[j][0]); upk2(g[2], g[3], acc[j][1]);
#pragma unroll
        for (int q = 0; q < 4; ++q) {
            float gg = g[q] + obv;
            if (!val || row == 0) gg = NEGV;
            float cc;
            if (val) {
                g_G[(size_t)bs[q] * VV + row] = gg;
                cc = g_cs[(size_t)bs[q] * VV + row];
            } else cc = NEGV;
            float nm = fmaxf(mloc[q], fmaxf(gg, cc));
            sloc[q] = sloc[q] * expf(mloc[q] - nm) + expf(gg - nm) + expf(cc - nm);
            mloc[q] = nm;
        }
    }
#pragma unroll
    for (int q = 0; q < 4; ++q) {
        s_m[bs[q] * 128 + ty] = mloc[q];
        s_s[bs[q] * 128 + ty] = sloc[q];
    }
    __syncthreads();
    if (tid < 16) {
        float M = -3.4e38f;
        for (int t = 0; t < 128; ++t) M = fmaxf(M, s_m[tid * 128 + t]);
        float S = 0.f;
        for (int t = 0; t < 128; ++t) S += s_s[tid * 128 + t] * expf(s_m[tid * 128 + t] - M);
        g_bmax[tid * NBK + blk] = M;
        g_bsum[tid * NBK + blk] = S;
    }
}

// softmax combine + final probs + argmax
__global__ __launch_bounds__(256) void k6_final(int step, float* __restrict__ out) {
    __shared__ float s_red[256];
    __shared__ unsigned long long s_k[256];
    __shared__ float s_M, s_Zi;
    int b = blockIdx.y, tid = threadIdx.x;
    float lm = -3.4e38f;
    for (int i = tid; i < NBK; i += 256) lm = fmaxf(lm, g_bmax[b * NBK + i]);
    s_red[tid] = lm; __syncthreads();
    for (int o = 128; o > 0; o >>= 1) {
        if (tid < o) s_red[tid] = fmaxf(s_red[tid], s_red[tid + o]);
        __syncthreads();
    }
    if (tid == 0) s_M = s_red[0];
    __syncthreads();
    float M = s_M;
    float ls = 0.f;
    for (int i = tid; i < NBK; i += 256) ls += g_bsum[b * NBK + i] * expf(g_bmax[b * NBK + i] - M);
    s_red[tid] = ls; __syncthreads();
    for (int o = 128; o > 0; o >>= 1) {
        if (tid < o) s_red[tid] += s_red[tid + o];
        __syncthreads();
    }
    if (tid == 0) s_Zi = 1.f / s_red[0];
    __syncthreads();
    float Zi = s_Zi;

    int v = blockIdx.x * 256 + tid;
    float* orow = out + ((size_t)b * ML + step + 1) * VS;
    unsigned long long key = 0ull;
    if (v < VV) {
        float f = (expf(g_G[(size_t)b * VV + v] - M) + expf(g_cs[(size_t)b * VV + v] - M)) * Zi;
        orow[v] = f;
        unsigned int u = __float_as_uint(f);
        unsigned int mono = u ^ ((u >> 31) ? 0xFFFFFFFFu : 0x80000000u);
        key = ((unsigned long long)mono << 32) | (unsigned int)(0x7FFFFFFF - v);
    } else if (v < VS) {
        orow[v] = 0.f;
    }
    s_k[tid] = key;
    __syncthreads();
    for (int o = 128; o > 0; o >>= 1) {
        if (tid < o) s_k[tid] = max(s_k[tid], s_k[tid + o]);
        __syncthreads();
    }
    if (tid == 0 && s_k[0]) atomicMax(&g_amax[b], s_k[0]);
}

extern "C" void kernel_launch(void* const* d_in, const int* in_sizes, int n_in,
                              void* d_out, int out_size) {
    const float* enc = (const float*)d_in[0];
    const float* tmo = (const float*)d_in[1];
    const float* z = (const float*)d_in[2];
    const float* emb = (const float*)d_in[3];
    const float* wih = (const float*)d_in[4];
    const float* whh = (const float*)d_in[5];
    const float* bih = (const float*)d_in[6];
    const float* bhh = (const float*)d_in[7];
    const float* aw = (const float*)d_in[8];
    const float* ab = (const float*)d_in[9];
    const float* cw = (const float*)d_in[10];
    const float* cb = (const float*)d_in[11];
    const float* ow = (const float*)d_in[12];
    const float* obp = (const float*)d_in[13];
    const int* tpl = (const int*)d_in[14];
    const int* inp = (const int*)d_in[15];
    float* out = (float*)d_out;
    float* oidx = (out_size >= BB * ML * VS + BB * ML) ? out + (size_t)BB * ML * VS : nullptr;

    const int k4smem = (16384 + 3 * 9216) * 4;  // 176128 B
    cudaFuncSetAttribute((const void*)k4_gen, cudaFuncAttributeMaxDynamicSharedMemorySize, k4smem);

    k3pre<<<dim3(16, BB), 256>>>(enc, aw, ab, cw, cb);
    for (int s = 0; s < ML - 1; ++s) {
        k1_prep<<<BB, 512>>>(s, z, enc, tmo, emb, tpl, inp, out, oidx);
        k2_mm<<<96, 256>>>(wih, whh);
        k3_attn<<<BB, 256>>>(enc, bih, bhh, inp);
        k4_gen<<<NBK, 512, k4smem>>>(ow, obp);
        k6_final<<<dim3(118, BB), 256>>>(s, out);
    }
}